// round 1
// baseline (speedup 1.0000x reference)
#include <cuda_runtime.h>
#include <math.h>

#define NQ     8192
#define NKV    2048
#define CDIM   512
#define HEADS  8
#define DH     64
#define FF     1024
#define LN_EPS 1e-5f

// ---------------- scratch (device globals; no runtime allocation) ----------------
__device__ float g_qn[NQ * CDIM];
__device__ float g_kn[NKV * CDIM];
__device__ float g_vn[NKV * CDIM];
__device__ float g_qh[NQ * CDIM];
__device__ float g_kh[NKV * CDIM];
__device__ float g_vh[NKV * CDIM];
__device__ float g_at[NQ * CDIM];
__device__ float g_z0[NQ * CDIM];
__device__ float g_z1[NQ * CDIM];
__device__ float g_h1[NQ * FF];
__device__ float g_z2[NQ * CDIM];
__device__ float g_muq[NQ],  g_rsq[NQ];
__device__ float g_muk[NKV], g_rsk[NKV];
__device__ float g_muv[NKV], g_rsv[NKV];
__device__ float g_mu2[NQ],  g_rs2[NQ];

// ---------------- LN stats for channel-major input (C, N) ----------------
__global__ void ln_stats_cm(const float* __restrict__ x, float* __restrict__ mu,
                            float* __restrict__ rs, int N) {
    int tok = blockIdx.x * blockDim.x + threadIdx.x;
    float s = 0.f, s2 = 0.f;
    for (int ch = 0; ch < CDIM; ch++) {
        float v = x[(size_t)ch * N + tok];
        s += v; s2 += v * v;
    }
    float m = s * (1.0f / CDIM);
    float var = s2 * (1.0f / CDIM) - m * m;
    mu[tok] = m;
    rs[tok] = rsqrtf(var + LN_EPS);
}

// ---------------- LN apply + transpose: (C, N) channel-major -> (N, C) row-major ----------------
__global__ void ln_apply_t_cm(const float* __restrict__ x, const float* __restrict__ mu,
                              const float* __restrict__ rs, const float* __restrict__ g,
                              const float* __restrict__ b, float* __restrict__ y, int N) {
    __shared__ float t[32][33];
    int n0 = blockIdx.x * 32, c0 = blockIdx.y * 32;
    int tx = threadIdx.x, ty = threadIdx.y;
#pragma unroll
    for (int i = 0; i < 4; i++) {
        int ch = c0 + ty + i * 8;
        t[ty + i * 8][tx] = x[(size_t)ch * N + n0 + tx];
    }
    __syncthreads();
#pragma unroll
    for (int i = 0; i < 4; i++) {
        int tok = n0 + ty + i * 8;
        int ch = c0 + tx;
        y[(size_t)tok * CDIM + ch] = (t[tx][ty + i * 8] - mu[tok]) * rs[tok] * g[ch] + b[ch];
    }
}

// ---------------- fused row LN: (N, C) row-major, LN over contiguous C ----------------
__global__ void ln_rows(const float* __restrict__ x, const float* __restrict__ g,
                        const float* __restrict__ b, float* __restrict__ y) {
    int row = blockIdx.x;
    int tid = threadIdx.x;                    // 256 threads, 2 elems each
    const float* xr = x + (size_t)row * CDIM;
    float v0 = xr[tid], v1 = xr[tid + 256];
    float s = v0 + v1, s2 = v0 * v0 + v1 * v1;
#pragma unroll
    for (int o = 16; o > 0; o >>= 1) {
        s  += __shfl_xor_sync(0xffffffffu, s,  o);
        s2 += __shfl_xor_sync(0xffffffffu, s2, o);
    }
    __shared__ float sw[8], sw2[8];
    if ((tid & 31) == 0) { sw[tid >> 5] = s; sw2[tid >> 5] = s2; }
    __syncthreads();
    float ts = 0.f, ts2 = 0.f;
#pragma unroll
    for (int i = 0; i < 8; i++) { ts += sw[i]; ts2 += sw2[i]; }
    float m = ts * (1.0f / CDIM);
    float rstd = rsqrtf(ts2 * (1.0f / CDIM) - m * m + LN_EPS);
    float* yr = y + (size_t)row * CDIM;
    yr[tid]       = (v0 - m) * rstd * g[tid]       + b[tid];
    yr[tid + 256] = (v1 - m) * rstd * g[tid + 256] + b[tid + 256];
}

// ---------------- row stats only ----------------
__global__ void row_stats(const float* __restrict__ x, float* __restrict__ mu,
                          float* __restrict__ rs) {
    int row = blockIdx.x;
    int tid = threadIdx.x;
    const float* xr = x + (size_t)row * CDIM;
    float v0 = xr[tid], v1 = xr[tid + 256];
    float s = v0 + v1, s2 = v0 * v0 + v1 * v1;
#pragma unroll
    for (int o = 16; o > 0; o >>= 1) {
        s  += __shfl_xor_sync(0xffffffffu, s,  o);
        s2 += __shfl_xor_sync(0xffffffffu, s2, o);
    }
    __shared__ float sw[8], sw2[8];
    if ((tid & 31) == 0) { sw[tid >> 5] = s; sw2[tid >> 5] = s2; }
    __syncthreads();
    if (tid == 0) {
        float ts = 0.f, ts2 = 0.f;
#pragma unroll
        for (int i = 0; i < 8; i++) { ts += sw[i]; ts2 += sw2[i]; }
        float m = ts * (1.0f / CDIM);
        mu[row] = m;
        rs[row] = rsqrtf(ts2 * (1.0f / CDIM) - m * m + LN_EPS);
    }
}

// ---------------- LN apply + transpose: (N, C) row-major -> (C, N) channel-major ----------------
__global__ void ln_apply_t_rm(const float* __restrict__ z, const float* __restrict__ mu,
                              const float* __restrict__ rs, const float* __restrict__ g,
                              const float* __restrict__ b, float* __restrict__ out, int N) {
    __shared__ float t[32][33];
    int t0 = blockIdx.x * 32, c0 = blockIdx.y * 32;
    int tx = threadIdx.x, ty = threadIdx.y;
#pragma unroll
    for (int i = 0; i < 4; i++) {
        int tok = t0 + ty + i * 8;
        t[ty + i * 8][tx] = z[(size_t)tok * CDIM + c0 + tx];
    }
    __syncthreads();
#pragma unroll
    for (int i = 0; i < 4; i++) {
        int ch = c0 + ty + i * 8;
        int tok = t0 + tx;
        out[(size_t)ch * N + tok] = (t[tx][ty + i * 8] - mu[tok]) * rs[tok] * g[ch] + b[ch];
    }
}

// ---------------- generic tiled GEMM: C = A(MxK) @ B(KxN) + bias [, gelu][, +res] ----------------
__global__ __launch_bounds__(256) void gemm128(
        const float* __restrict__ A, const float* __restrict__ B,
        const float* __restrict__ bias, const float* __restrict__ res,
        float* __restrict__ Cmat, int M, int N, int K, int doGelu) {
    __shared__ float As[8 * 128];   // [k][m]
    __shared__ float Bs[8 * 128];   // [k][n]
    int tid = threadIdx.x;
    int n0 = blockIdx.x * 128, m0 = blockIdx.y * 128;
    int tx = tid & 15, ty = tid >> 4;
    float acc[8][8];
#pragma unroll
    for (int i = 0; i < 8; i++)
#pragma unroll
        for (int j = 0; j < 8; j++) acc[i][j] = 0.f;

    int la_m = tid >> 1, la_k4 = (tid & 1) * 4;
    int lb_k = tid >> 5, lb_n = (tid & 31) * 4;
    const float* ap = A + (size_t)(m0 + la_m) * K + la_k4;
    const float* bp = B + (size_t)lb_k * N + n0 + lb_n;
    const float4* As4 = (const float4*)As;
    const float4* Bs4 = (const float4*)Bs;

    for (int k0 = 0; k0 < K; k0 += 8) {
        __syncthreads();
        float4 av = *(const float4*)ap; ap += 8;
        As[(la_k4 + 0) * 128 + la_m] = av.x;
        As[(la_k4 + 1) * 128 + la_m] = av.y;
        As[(la_k4 + 2) * 128 + la_m] = av.z;
        As[(la_k4 + 3) * 128 + la_m] = av.w;
        *(float4*)&Bs[lb_k * 128 + lb_n] = *(const float4*)bp; bp += (size_t)8 * N;
        __syncthreads();
#pragma unroll
        for (int k = 0; k < 8; k++) {
            float4 a0 = As4[k * 32 + ty];
            float4 a1 = As4[k * 32 + 16 + ty];
            float4 b0 = Bs4[k * 32 + tx];
            float4 b1 = Bs4[k * 32 + 16 + tx];
            float ar[8] = {a0.x, a0.y, a0.z, a0.w, a1.x, a1.y, a1.z, a1.w};
            float br[8] = {b0.x, b0.y, b0.z, b0.w, b1.x, b1.y, b1.z, b1.w};
#pragma unroll
            for (int i = 0; i < 8; i++)
#pragma unroll
                for (int j = 0; j < 8; j++)
                    acc[i][j] = fmaf(ar[i], br[j], acc[i][j]);
        }
    }
#pragma unroll
    for (int i = 0; i < 8; i++) {
        int row = m0 + ((i < 4) ? (ty * 4 + i) : (64 + ty * 4 + i - 4));
#pragma unroll
        for (int j = 0; j < 8; j++) {
            int col = n0 + ((j < 4) ? (tx * 4 + j) : (64 + tx * 4 + j - 4));
            float c = acc[i][j] + bias[col];
            if (doGelu) c = 0.5f * c * (1.0f + erff(c * 0.70710678118654752f));
            if (res) c += res[(size_t)row * N + col];
            Cmat[(size_t)row * N + col] = c;
        }
    }
}

// ---------------- flash attention: 64 queries x 1 head per block ----------------
__global__ __launch_bounds__(256) void attn_kernel(
        const float* __restrict__ qh, const float* __restrict__ kh,
        const float* __restrict__ vh, float* __restrict__ outp) {
    __shared__ float Qs[64 * 64];   // [c][r]
    __shared__ float Ks[64 * 64];   // [c][n] during S; reused as P [r][n]
    __shared__ float Vs[64 * 64];   // [n][d]
    const int tid = threadIdx.x;
    const int h  = blockIdx.y;
    const int q0 = blockIdx.x * 64;
    const int tx = tid & 15, ty = tid >> 4;

    {   // load Q (pre-scaled by 1/sqrt(64))
        int r = tid >> 2;
        int cq = (tid & 3) * 16;
        const float* src = qh + (size_t)(q0 + r) * CDIM + h * DH + cq;
#pragma unroll
        for (int i = 0; i < 4; i++) {
            float4 t = *(const float4*)(src + 4 * i);
            int c = cq + 4 * i;
            Qs[(c + 0) * 64 + r] = t.x * 0.125f;
            Qs[(c + 1) * 64 + r] = t.y * 0.125f;
            Qs[(c + 2) * 64 + r] = t.z * 0.125f;
            Qs[(c + 3) * 64 + r] = t.w * 0.125f;
        }
    }
    float m[4], l[4], O[4][4];
#pragma unroll
    for (int i = 0; i < 4; i++) {
        m[i] = -1e30f; l[i] = 0.f;
#pragma unroll
        for (int j = 0; j < 4; j++) O[i][j] = 0.f;
    }

    for (int k0 = 0; k0 < NKV; k0 += 64) {
        __syncthreads();   // previous iter done with Ks(P) / Vs
        {   // load K tile (transposed [c][n]) and V tile ([n][d])
            int n = tid >> 2;
            int cq = (tid & 3) * 16;
            const float* ks = kh + (size_t)(k0 + n) * CDIM + h * DH + cq;
            const float* vs = vh + (size_t)(k0 + n) * CDIM + h * DH + cq;
#pragma unroll
            for (int i = 0; i < 4; i++) {
                float4 t = *(const float4*)(ks + 4 * i);
                int c = cq + 4 * i;
                Ks[(c + 0) * 64 + n] = t.x;
                Ks[(c + 1) * 64 + n] = t.y;
                Ks[(c + 2) * 64 + n] = t.z;
                Ks[(c + 3) * 64 + n] = t.w;
                *(float4*)&Vs[n * 64 + c] = *(const float4*)(vs + 4 * i);
            }
        }
        __syncthreads();

        float S[4][4];
#pragma unroll
        for (int i = 0; i < 4; i++)
#pragma unroll
            for (int j = 0; j < 4; j++) S[i][j] = 0.f;
        const float4* Q4 = (const float4*)Qs;
        const float4* K4 = (const float4*)Ks;
#pragma unroll 8
        for (int c = 0; c < 64; c++) {
            float4 a  = Q4[c * 16 + ty];
            float4 bb = K4[c * 16 + tx];
            float ar[4] = {a.x, a.y, a.z, a.w};
            float br[4] = {bb.x, bb.y, bb.z, bb.w};
#pragma unroll
            for (int i = 0; i < 4; i++)
#pragma unroll
                for (int j = 0; j < 4; j++)
                    S[i][j] = fmaf(ar[i], br[j], S[i][j]);
        }

        // online softmax across the 16 tx lanes (butterfly within warp halves)
#pragma unroll
        for (int i = 0; i < 4; i++) {
            float mt = fmaxf(fmaxf(S[i][0], S[i][1]), fmaxf(S[i][2], S[i][3]));
#pragma unroll
            for (int o = 1; o < 16; o <<= 1)
                mt = fmaxf(mt, __shfl_xor_sync(0xffffffffu, mt, o));
            float mn = fmaxf(m[i], mt);
            float corr = __expf(m[i] - mn);
            float rsum = 0.f;
#pragma unroll
            for (int j = 0; j < 4; j++) {
                S[i][j] = __expf(S[i][j] - mn);
                rsum += S[i][j];
            }
#pragma unroll
            for (int o = 1; o < 16; o <<= 1)
                rsum += __shfl_xor_sync(0xffffffffu, rsum, o);
            l[i] = l[i] * corr + rsum;
#pragma unroll
            for (int j = 0; j < 4; j++) O[i][j] *= corr;
            m[i] = mn;
        }
        __syncthreads();   // everyone done reading Ks for S

        // write P into Ks as [r][n] (conflict-free float4 stores)
        float4* P4 = (float4*)Ks;
#pragma unroll
        for (int i = 0; i < 4; i++)
            P4[(4 * ty + i) * 16 + tx] = make_float4(S[i][0], S[i][1], S[i][2], S[i][3]);
        __syncthreads();

        // O += P @ V
        const float* Ps = Ks;
        const float4* V4 = (const float4*)Vs;
#pragma unroll 8
        for (int n = 0; n < 64; n++) {
            float4 vv = V4[n * 16 + tx];
            float vr[4] = {vv.x, vv.y, vv.z, vv.w};
#pragma unroll
            for (int i = 0; i < 4; i++) {
                float p = Ps[(4 * ty + i) * 64 + n];
#pragma unroll
                for (int j = 0; j < 4; j++)
                    O[i][j] = fmaf(p, vr[j], O[i][j]);
            }
        }
    }

#pragma unroll
    for (int i = 0; i < 4; i++) {
        float inv = 1.0f / l[i];
        int row = q0 + 4 * ty + i;
        float4 o4 = make_float4(O[i][0] * inv, O[i][1] * inv, O[i][2] * inv, O[i][3] * inv);
        *(float4*)&outp[(size_t)row * CDIM + h * DH + 4 * tx] = o4;
    }
}

// ---------------- launch ----------------
extern "C" void kernel_launch(void* const* d_in, const int* in_sizes, int n_in,
                              void* d_out, int out_size) {
    const float* q        = (const float*)d_in[0];
    const float* k        = (const float*)d_in[1];
    const float* v        = (const float*)d_in[2];
    const float* ln_q_g   = (const float*)d_in[3];
    const float* ln_q_b   = (const float*)d_in[4];
    const float* ln_k_g   = (const float*)d_in[5];
    const float* ln_k_b   = (const float*)d_in[6];
    const float* ln_v_g   = (const float*)d_in[7];
    const float* ln_v_b   = (const float*)d_in[8];
    const float* Wq       = (const float*)d_in[9];
    const float* bq       = (const float*)d_in[10];
    const float* Wk       = (const float*)d_in[11];
    const float* bk       = (const float*)d_in[12];
    const float* Wv       = (const float*)d_in[13];
    const float* bv       = (const float*)d_in[14];
    const float* Wp       = (const float*)d_in[15];
    const float* bp       = (const float*)d_in[16];
    const float* ln_pre_g = (const float*)d_in[17];
    const float* ln_pre_b = (const float*)d_in[18];
    const float* W1       = (const float*)d_in[19];
    const float* b1       = (const float*)d_in[20];
    const float* W2       = (const float*)d_in[21];
    const float* b2       = (const float*)d_in[22];
    const float* ln_po_g  = (const float*)d_in[23];
    const float* ln_po_b  = (const float*)d_in[24];
    float* out = (float*)d_out;

    float *qn, *kn, *vn, *qh, *kh, *vh, *at, *z0, *z1, *h1, *z2;
    float *muq, *rsq, *muk, *rsk, *muv, *rsv, *mu2, *rs2;
    cudaGetSymbolAddress((void**)&qn, g_qn);
    cudaGetSymbolAddress((void**)&kn, g_kn);
    cudaGetSymbolAddress((void**)&vn, g_vn);
    cudaGetSymbolAddress((void**)&qh, g_qh);
    cudaGetSymbolAddress((void**)&kh, g_kh);
    cudaGetSymbolAddress((void**)&vh, g_vh);
    cudaGetSymbolAddress((void**)&at, g_at);
    cudaGetSymbolAddress((void**)&z0, g_z0);
    cudaGetSymbolAddress((void**)&z1, g_z1);
    cudaGetSymbolAddress((void**)&h1, g_h1);
    cudaGetSymbolAddress((void**)&z2, g_z2);
    cudaGetSymbolAddress((void**)&muq, g_muq);
    cudaGetSymbolAddress((void**)&rsq, g_rsq);
    cudaGetSymbolAddress((void**)&muk, g_muk);
    cudaGetSymbolAddress((void**)&rsk, g_rsk);
    cudaGetSymbolAddress((void**)&muv, g_muv);
    cudaGetSymbolAddress((void**)&rsv, g_rsv);
    cudaGetSymbolAddress((void**)&mu2, g_mu2);
    cudaGetSymbolAddress((void**)&rs2, g_rs2);

    dim3 tblk(32, 8);

    // 1) input LNs (channel-major) + transpose to token-major
    ln_stats_cm<<<NQ / 256, 256>>>(q, muq, rsq, NQ);
    ln_stats_cm<<<NKV / 256, 256>>>(k, muk, rsk, NKV);
    ln_stats_cm<<<NKV / 256, 256>>>(v, muv, rsv, NKV);
    ln_apply_t_cm<<<dim3(NQ / 32, CDIM / 32), tblk>>>(q, muq, rsq, ln_q_g, ln_q_b, qn, NQ);
    ln_apply_t_cm<<<dim3(NKV / 32, CDIM / 32), tblk>>>(k, muk, rsk, ln_k_g, ln_k_b, kn, NKV);
    ln_apply_t_cm<<<dim3(NKV / 32, CDIM / 32), tblk>>>(v, muv, rsv, ln_v_g, ln_v_b, vn, NKV);

    // 2) QKV projections
    gemm128<<<dim3(CDIM / 128, NQ / 128), 256>>>(qn, Wq, bq, nullptr, qh, NQ, CDIM, CDIM, 0);
    gemm128<<<dim3(CDIM / 128, NKV / 128), 256>>>(kn, Wk, bk, nullptr, kh, NKV, CDIM, CDIM, 0);
    gemm128<<<dim3(CDIM / 128, NKV / 128), 256>>>(vn, Wv, bv, nullptr, vh, NKV, CDIM, CDIM, 0);

    // 3) flash attention
    attn_kernel<<<dim3(NQ / 64, HEADS), 256>>>(qh, kh, vh, at);

    // 4) output projection + pre-LN
    gemm128<<<dim3(CDIM / 128, NQ / 128), 256>>>(at, Wp, bp, nullptr, z0, NQ, CDIM, CDIM, 0);
    ln_rows<<<NQ, 256>>>(z0, ln_pre_g, ln_pre_b, z1);

    // 5) MLP with fused GELU and residual
    gemm128<<<dim3(FF / 128, NQ / 128), 256>>>(z1, W1, b1, nullptr, h1, NQ, FF, CDIM, 1);
    gemm128<<<dim3(CDIM / 128, NQ / 128), 256>>>(h1, W2, b2, z1, z2, NQ, CDIM, FF, 0);

    // 6) post-LN fused with transpose back to (C, N)
    row_stats<<<NQ, 256>>>(z2, mu2, rs2);
    ln_apply_t_rm<<<dim3(NQ / 32, CDIM / 32), tblk>>>(z2, mu2, rs2, ln_po_g, ln_po_b, out, NQ);
}

// round 2
// speedup vs baseline: 3.6321x; 3.6321x over previous
#include <cuda_runtime.h>
#include <cuda_fp16.h>
#include <mma.h>
#include <math.h>

using namespace nvcuda;

#define NQ     8192
#define NKV    2048
#define CDIM   512
#define HEADS  8
#define DH     64
#define FF     1024
#define LN_EPS 1e-5f

// ---------------- scratch (device globals) ----------------
__device__ __half g_qn[NQ * CDIM];
__device__ __half g_kn[NKV * CDIM];
__device__ __half g_vn[NKV * CDIM];
__device__ __half g_qh[NQ * CDIM];
__device__ __half g_kh[NKV * CDIM];
__device__ __half g_vh[NKV * CDIM];
__device__ __half g_at[NQ * CDIM];
__device__ __half g_z0[NQ * CDIM];
__device__ __half g_z1[NQ * CDIM];
__device__ __half g_h1[NQ * FF];
__device__ float  g_z2[NQ * CDIM];
__device__ __half g_Wqh[CDIM * CDIM];
__device__ __half g_Wkh[CDIM * CDIM];
__device__ __half g_Wvh[CDIM * CDIM];
__device__ __half g_Wph[CDIM * CDIM];
__device__ __half g_W1h[CDIM * FF];
__device__ __half g_W2h[FF * CDIM];
__device__ float g_muq[NQ],  g_rsq[NQ];
__device__ float g_muk[NKV], g_rsk[NKV];
__device__ float g_muv[NKV], g_rsv[NKV];
__device__ float g_mu2[NQ],  g_rs2[NQ];

// ---------------- fp32 -> fp16 convert (2 elems / thread) ----------------
__global__ void f2h(const float* __restrict__ x, __half* __restrict__ y, int n2) {
    int i = blockIdx.x * blockDim.x + threadIdx.x;
    if (i < n2) {
        float2 v = ((const float2*)x)[i];
        ((half2*)y)[i] = __floats2half2_rn(v.x, v.y);
    }
}

// ---------------- LN stats for channel-major input (C, N) ----------------
__global__ void ln_stats_cm(const float* __restrict__ x, float* __restrict__ mu,
                            float* __restrict__ rs, int N) {
    int tok = blockIdx.x * blockDim.x + threadIdx.x;
    float s = 0.f, s2 = 0.f;
    for (int ch = 0; ch < CDIM; ch++) {
        float v = x[(size_t)ch * N + tok];
        s += v; s2 += v * v;
    }
    float m = s * (1.0f / CDIM);
    float var = s2 * (1.0f / CDIM) - m * m;
    mu[tok] = m;
    rs[tok] = rsqrtf(var + LN_EPS);
}

// ---------------- LN apply + transpose: (C, N) -> (N, C) fp16 ----------------
__global__ void ln_apply_t_cm(const float* __restrict__ x, const float* __restrict__ mu,
                              const float* __restrict__ rs, const float* __restrict__ g,
                              const float* __restrict__ b, __half* __restrict__ y, int N) {
    __shared__ float t[32][33];
    int n0 = blockIdx.x * 32, c0 = blockIdx.y * 32;
    int tx = threadIdx.x, ty = threadIdx.y;
#pragma unroll
    for (int i = 0; i < 4; i++) {
        int ch = c0 + ty + i * 8;
        t[ty + i * 8][tx] = x[(size_t)ch * N + n0 + tx];
    }
    __syncthreads();
#pragma unroll
    for (int i = 0; i < 4; i++) {
        int tok = n0 + ty + i * 8;
        int ch = c0 + tx;
        float v = (t[tx][ty + i * 8] - mu[tok]) * rs[tok] * g[ch] + b[ch];
        y[(size_t)tok * CDIM + ch] = __float2half_rn(v);
    }
}

// ---------------- row LN: fp16 in/out, stats in fp32 ----------------
__global__ void ln_rows_h(const __half* __restrict__ x, const float* __restrict__ g,
                          const float* __restrict__ b, __half* __restrict__ y) {
    int row = blockIdx.x;
    int tid = threadIdx.x;
    const __half* xr = x + (size_t)row * CDIM;
    float v0 = __half2float(xr[tid]), v1 = __half2float(xr[tid + 256]);
    float s = v0 + v1, s2 = v0 * v0 + v1 * v1;
#pragma unroll
    for (int o = 16; o > 0; o >>= 1) {
        s  += __shfl_xor_sync(0xffffffffu, s,  o);
        s2 += __shfl_xor_sync(0xffffffffu, s2, o);
    }
    __shared__ float sw[8], sw2[8];
    if ((tid & 31) == 0) { sw[tid >> 5] = s; sw2[tid >> 5] = s2; }
    __syncthreads();
    float ts = 0.f, ts2 = 0.f;
#pragma unroll
    for (int i = 0; i < 8; i++) { ts += sw[i]; ts2 += sw2[i]; }
    float m = ts * (1.0f / CDIM);
    float rstd = rsqrtf(ts2 * (1.0f / CDIM) - m * m + LN_EPS);
    __half* yr = y + (size_t)row * CDIM;
    yr[tid]       = __float2half_rn((v0 - m) * rstd * g[tid]       + b[tid]);
    yr[tid + 256] = __float2half_rn((v1 - m) * rstd * g[tid + 256] + b[tid + 256]);
}

// ---------------- row stats (fp32 input) ----------------
__global__ void row_stats(const float* __restrict__ x, float* __restrict__ mu,
                          float* __restrict__ rs) {
    int row = blockIdx.x;
    int tid = threadIdx.x;
    const float* xr = x + (size_t)row * CDIM;
    float v0 = xr[tid], v1 = xr[tid + 256];
    float s = v0 + v1, s2 = v0 * v0 + v1 * v1;
#pragma unroll
    for (int o = 16; o > 0; o >>= 1) {
        s  += __shfl_xor_sync(0xffffffffu, s,  o);
        s2 += __shfl_xor_sync(0xffffffffu, s2, o);
    }
    __shared__ float sw[8], sw2[8];
    if ((tid & 31) == 0) { sw[tid >> 5] = s; sw2[tid >> 5] = s2; }
    __syncthreads();
    if (tid == 0) {
        float ts = 0.f, ts2 = 0.f;
#pragma unroll
        for (int i = 0; i < 8; i++) { ts += sw[i]; ts2 += sw2[i]; }
        float m = ts * (1.0f / CDIM);
        mu[row] = m;
        rs[row] = rsqrtf(ts2 * (1.0f / CDIM) - m * m + LN_EPS);
    }
}

// ---------------- LN apply + transpose: (N, C) fp32 -> (C, N) fp32 ----------------
__global__ void ln_apply_t_rm(const float* __restrict__ z, const float* __restrict__ mu,
                              const float* __restrict__ rs, const float* __restrict__ g,
                              const float* __restrict__ b, float* __restrict__ out, int N) {
    __shared__ float t[32][33];
    int t0 = blockIdx.x * 32, c0 = blockIdx.y * 32;
    int tx = threadIdx.x, ty = threadIdx.y;
#pragma unroll
    for (int i = 0; i < 4; i++) {
        int tok = t0 + ty + i * 8;
        t[ty + i * 8][tx] = z[(size_t)tok * CDIM + c0 + tx];
    }
    __syncthreads();
#pragma unroll
    for (int i = 0; i < 4; i++) {
        int ch = c0 + ty + i * 8;
        int tok = t0 + tx;
        out[(size_t)ch * N + tok] = (t[tx][ty + i * 8] - mu[tok]) * rs[tok] * g[ch] + b[ch];
    }
}

// ---------------- fp16 tensor-core GEMM: 128x128 tile, BK=32 ----------------
// C = A(MxK) @ B(KxN) + bias [, gelu][, +res(h)]; writes Ch (fp16) and/or Cf (fp32)
#define LDA_S 40
#define LDB_S 136
__global__ __launch_bounds__(256) void hgemm(
        const __half* __restrict__ A, const __half* __restrict__ B,
        const float* __restrict__ bias, const __half* __restrict__ res,
        __half* __restrict__ Ch, float* __restrict__ Cf,
        int M, int N, int K, int doGelu) {
    __shared__ __half As[128 * LDA_S];
    __shared__ __half Bs[32 * LDB_S];
    __shared__ float  sc[8][16 * 20];

    int tid = threadIdx.x;
    int lane = tid & 31;
    int w = tid >> 5;            // 0..7
    int wm = w >> 1, wn = w & 1; // warp tile: rows 32*wm, cols 64*wn
    int n0 = blockIdx.x * 128, m0 = blockIdx.y * 128;

    wmma::fragment<wmma::accumulator, 16, 16, 16, float> acc[2][4];
#pragma unroll
    for (int i = 0; i < 2; i++)
#pragma unroll
        for (int j = 0; j < 4; j++) wmma::fill_fragment(acc[i][j], 0.f);

    // A loader: thread t -> row t/2, col half (t&1)*16 (2x uint4 = 16 halfs)
    int ar = tid >> 1, ac = (tid & 1) * 16;
    // B loader: thread t -> row t/8, col (t&7)*16
    int br = tid >> 3, bc = (tid & 7) * 16;
    const __half* ap = A + (size_t)(m0 + ar) * K + ac;
    const __half* bp = B + (size_t)br * N + n0 + bc;

    for (int k0 = 0; k0 < K; k0 += 32) {
        __syncthreads();
        uint4 a0 = *(const uint4*)(ap);
        uint4 a1 = *(const uint4*)(ap + 8);
        ap += 32;
        *(uint4*)&As[ar * LDA_S + ac]     = a0;
        *(uint4*)&As[ar * LDA_S + ac + 8] = a1;
        uint4 b0 = *(const uint4*)(bp);
        uint4 b1 = *(const uint4*)(bp + 8);
        bp += (size_t)32 * N;
        *(uint4*)&Bs[br * LDB_S + bc]     = b0;
        *(uint4*)&Bs[br * LDB_S + bc + 8] = b1;
        __syncthreads();
#pragma unroll
        for (int ks = 0; ks < 2; ks++) {
            wmma::fragment<wmma::matrix_a, 16, 16, 16, __half, wmma::row_major> af[2];
            wmma::fragment<wmma::matrix_b, 16, 16, 16, __half, wmma::row_major> bf[4];
#pragma unroll
            for (int i = 0; i < 2; i++)
                wmma::load_matrix_sync(af[i], &As[(32 * wm + 16 * i) * LDA_S + 16 * ks], LDA_S);
#pragma unroll
            for (int j = 0; j < 4; j++)
                wmma::load_matrix_sync(bf[j], &Bs[(16 * ks) * LDB_S + 64 * wn + 16 * j], LDB_S);
#pragma unroll
            for (int i = 0; i < 2; i++)
#pragma unroll
                for (int j = 0; j < 4; j++)
                    wmma::mma_sync(acc[i][j], af[i], bf[j], acc[i][j]);
        }
    }

    // epilogue via per-warp smem staging
    int lr = lane >> 1, lc0 = (lane & 1) * 8;
#pragma unroll
    for (int i = 0; i < 2; i++) {
#pragma unroll
        for (int j = 0; j < 4; j++) {
            wmma::store_matrix_sync(&sc[w][0], acc[i][j], 20, wmma::mem_row_major);
            __syncwarp();
            int row = m0 + 32 * wm + 16 * i + lr;
            int col = n0 + 64 * wn + 16 * j + lc0;
            float vv[8];
#pragma unroll
            for (int e = 0; e < 8; e++) {
                float c = sc[w][lr * 20 + lc0 + e] + bias[col + e];
                if (doGelu) c = 0.5f * c * (1.0f + erff(c * 0.70710678118654752f));
                if (res) c += __half2float(res[(size_t)row * N + col + e]);
                vv[e] = c;
            }
            if (Ch) {
                half2* dst = (half2*)&Ch[(size_t)row * N + col];
                dst[0] = __floats2half2_rn(vv[0], vv[1]);
                dst[1] = __floats2half2_rn(vv[2], vv[3]);
                dst[2] = __floats2half2_rn(vv[4], vv[5]);
                dst[3] = __floats2half2_rn(vv[6], vv[7]);
            }
            if (Cf) {
                float4* dst = (float4*)&Cf[(size_t)row * N + col];
                dst[0] = make_float4(vv[0], vv[1], vv[2], vv[3]);
                dst[1] = make_float4(vv[4], vv[5], vv[6], vv[7]);
            }
            __syncwarp();
        }
    }
}

// ---------------- mma.sync helper ----------------
__device__ __forceinline__ void mma16816(float* c, const unsigned* a, const unsigned* b) {
    asm volatile(
        "mma.sync.aligned.m16n8k16.row.col.f32.f16.f16.f32 "
        "{%0,%1,%2,%3}, {%4,%5,%6,%7}, {%8,%9}, {%0,%1,%2,%3};"
        : "+f"(c[0]), "+f"(c[1]), "+f"(c[2]), "+f"(c[3])
        : "r"(a[0]), "r"(a[1]), "r"(a[2]), "r"(a[3]), "r"(b[0]), "r"(b[1]));
}

// ---------------- flash attention (fp16 mma, fp32 softmax) ----------------
// Block: 128 threads (4 warps), 64 queries x 1 head; Bk = 64 KV per iter.
#define LDK 72
__global__ __launch_bounds__(128) void attn_h(
        const __half* __restrict__ qh, const __half* __restrict__ kh,
        const __half* __restrict__ vh, __half* __restrict__ outp) {
    __shared__ __half Ks[64 * LDK];   // [tok][d] (also Q staging in prologue)
    __shared__ __half Vt[64 * LDK];   // [d][tok]

    const int tid = threadIdx.x;
    const int lane = tid & 31;
    const int w = tid >> 5;          // warp 0..3, owns rows 16w..16w+15
    const int h = blockIdx.y;
    const int q0 = blockIdx.x * 64;
    const int tq = lane >> 2;        // 0..7  (row group)
    const int tr = lane & 3;         // 0..3  (col quad)

    // ---- stage Q tile into Ks (scaled by 1/8), build A-fragments ----
    {
        int tok = tid >> 1, cb = (tid & 1) * 32;
        const __half* src = qh + (size_t)(q0 + tok) * CDIM + h * DH + cb;
        half2 scale = __half2half2(__float2half(0.125f));
#pragma unroll
        for (int i = 0; i < 4; i++) {
            half2 p0 = ((const half2*)src)[i * 4 + 0];
            half2 p1 = ((const half2*)src)[i * 4 + 1];
            half2 p2 = ((const half2*)src)[i * 4 + 2];
            half2 p3 = ((const half2*)src)[i * 4 + 3];
            half2* d = (half2*)&Ks[tok * LDK + cb + i * 8];
            d[0] = __hmul2(p0, scale);
            d[1] = __hmul2(p1, scale);
            d[2] = __hmul2(p2, scale);
            d[3] = __hmul2(p3, scale);
        }
    }
    __syncthreads();
    unsigned qa[4][4];
#pragma unroll
    for (int c = 0; c < 4; c++) {
        int r0 = 16 * w + tq, r1 = r0 + 8;
        int d0 = c * 16 + 2 * tr;
        qa[c][0] = *(const unsigned*)&Ks[r0 * LDK + d0];
        qa[c][1] = *(const unsigned*)&Ks[r1 * LDK + d0];
        qa[c][2] = *(const unsigned*)&Ks[r0 * LDK + d0 + 8];
        qa[c][3] = *(const unsigned*)&Ks[r1 * LDK + d0 + 8];
    }
    __syncthreads();

    float m0 = -1e30f, m1 = -1e30f, l0 = 0.f, l1 = 0.f;
    float oacc[8][4];
#pragma unroll
    for (int j = 0; j < 8; j++)
#pragma unroll
        for (int r = 0; r < 4; r++) oacc[j][r] = 0.f;

    for (int k0 = 0; k0 < NKV; k0 += 64) {
        // ---- load K tile (row-major) and V tile (transposed) ----
        {
            int tok = tid >> 1, cb = (tid & 1) * 32;
            const __half* ksrc = kh + (size_t)(k0 + tok) * CDIM + h * DH + cb;
            const __half* vsrc = vh + (size_t)(k0 + tok) * CDIM + h * DH + cb;
            uint4 k0v = ((const uint4*)ksrc)[0];
            uint4 k1v = ((const uint4*)ksrc)[1];
            uint4 k2v = ((const uint4*)ksrc)[2];
            uint4 k3v = ((const uint4*)ksrc)[3];
            *(uint4*)&Ks[tok * LDK + cb]      = k0v;
            *(uint4*)&Ks[tok * LDK + cb + 8]  = k1v;
            *(uint4*)&Ks[tok * LDK + cb + 16] = k2v;
            *(uint4*)&Ks[tok * LDK + cb + 24] = k3v;
            __half vbuf[32];
            *(uint4*)&vbuf[0]  = ((const uint4*)vsrc)[0];
            *(uint4*)&vbuf[8]  = ((const uint4*)vsrc)[1];
            *(uint4*)&vbuf[16] = ((const uint4*)vsrc)[2];
            *(uint4*)&vbuf[24] = ((const uint4*)vsrc)[3];
#pragma unroll
            for (int i = 0; i < 32; i++)
                Vt[(cb + i) * LDK + tok] = vbuf[i];
        }
        __syncthreads();

        // ---- S = Qs @ K^T ----
        float sacc[8][4];
#pragma unroll
        for (int j = 0; j < 8; j++)
#pragma unroll
            for (int r = 0; r < 4; r++) sacc[j][r] = 0.f;
#pragma unroll
        for (int j = 0; j < 8; j++) {
            int tok = j * 8 + tq;
#pragma unroll
            for (int c = 0; c < 4; c++) {
                unsigned bb[2];
                bb[0] = *(const unsigned*)&Ks[tok * LDK + c * 16 + 2 * tr];
                bb[1] = *(const unsigned*)&Ks[tok * LDK + c * 16 + 2 * tr + 8];
                mma16816(sacc[j], qa[c], bb);
            }
        }

        // ---- online softmax (rows r0 = regs 0,1; r1 = regs 2,3) ----
        float mx0 = -1e30f, mx1 = -1e30f;
#pragma unroll
        for (int j = 0; j < 8; j++) {
            mx0 = fmaxf(mx0, fmaxf(sacc[j][0], sacc[j][1]));
            mx1 = fmaxf(mx1, fmaxf(sacc[j][2], sacc[j][3]));
        }
        mx0 = fmaxf(mx0, __shfl_xor_sync(0xffffffffu, mx0, 1));
        mx0 = fmaxf(mx0, __shfl_xor_sync(0xffffffffu, mx0, 2));
        mx1 = fmaxf(mx1, __shfl_xor_sync(0xffffffffu, mx1, 1));
        mx1 = fmaxf(mx1, __shfl_xor_sync(0xffffffffu, mx1, 2));
        float mn0 = fmaxf(m0, mx0), mn1 = fmaxf(m1, mx1);
        float corr0 = __expf(m0 - mn0), corr1 = __expf(m1 - mn1);
        m0 = mn0; m1 = mn1;
        float s0 = 0.f, s1 = 0.f;
#pragma unroll
        for (int j = 0; j < 8; j++) {
            sacc[j][0] = __expf(sacc[j][0] - mn0);
            sacc[j][1] = __expf(sacc[j][1] - mn0);
            sacc[j][2] = __expf(sacc[j][2] - mn1);
            sacc[j][3] = __expf(sacc[j][3] - mn1);
            s0 += sacc[j][0] + sacc[j][1];
            s1 += sacc[j][2] + sacc[j][3];
        }
        s0 += __shfl_xor_sync(0xffffffffu, s0, 1);
        s0 += __shfl_xor_sync(0xffffffffu, s0, 2);
        s1 += __shfl_xor_sync(0xffffffffu, s1, 1);
        s1 += __shfl_xor_sync(0xffffffffu, s1, 2);
        l0 = l0 * corr0 + s0;
        l1 = l1 * corr1 + s1;
#pragma unroll
        for (int j = 0; j < 8; j++) {
            oacc[j][0] *= corr0; oacc[j][1] *= corr0;
            oacc[j][2] *= corr1; oacc[j][3] *= corr1;
        }

        // ---- P fragments (register-only from S accumulators) ----
        unsigned pa[4][4];
#pragma unroll
        for (int c = 0; c < 4; c++) {
            half2 h0 = __floats2half2_rn(sacc[2 * c][0], sacc[2 * c][1]);
            half2 h1v = __floats2half2_rn(sacc[2 * c][2], sacc[2 * c][3]);
            half2 h2 = __floats2half2_rn(sacc[2 * c + 1][0], sacc[2 * c + 1][1]);
            half2 h3 = __floats2half2_rn(sacc[2 * c + 1][2], sacc[2 * c + 1][3]);
            pa[c][0] = *(unsigned*)&h0;
            pa[c][1] = *(unsigned*)&h1v;
            pa[c][2] = *(unsigned*)&h2;
            pa[c][3] = *(unsigned*)&h3;
        }

        // ---- O += P @ V ----
#pragma unroll
        for (int j = 0; j < 8; j++) {
            int d = j * 8 + tq;
#pragma unroll
            for (int c = 0; c < 4; c++) {
                unsigned bb[2];
                bb[0] = *(const unsigned*)&Vt[d * LDK + c * 16 + 2 * tr];
                bb[1] = *(const unsigned*)&Vt[d * LDK + c * 16 + 2 * tr + 8];
                mma16816(oacc[j], pa[c], bb);
            }
        }
        __syncthreads();
    }

    // ---- normalize + write ----
    float inv0 = 1.0f / l0, inv1 = 1.0f / l1;
    int r0 = q0 + 16 * w + tq, r1 = r0 + 8;
#pragma unroll
    for (int j = 0; j < 8; j++) {
        int col = h * DH + j * 8 + 2 * tr;
        *(half2*)&outp[(size_t)r0 * CDIM + col] = __floats2half2_rn(oacc[j][0] * inv0, oacc[j][1] * inv0);
        *(half2*)&outp[(size_t)r1 * CDIM + col] = __floats2half2_rn(oacc[j][2] * inv1, oacc[j][3] * inv1);
    }
}

// ---------------- launch ----------------
extern "C" void kernel_launch(void* const* d_in, const int* in_sizes, int n_in,
                              void* d_out, int out_size) {
    const float* q        = (const float*)d_in[0];
    const float* k        = (const float*)d_in[1];
    const float* v        = (const float*)d_in[2];
    const float* ln_q_g   = (const float*)d_in[3];
    const float* ln_q_b   = (const float*)d_in[4];
    const float* ln_k_g   = (const float*)d_in[5];
    const float* ln_k_b   = (const float*)d_in[6];
    const float* ln_v_g   = (const float*)d_in[7];
    const float* ln_v_b   = (const float*)d_in[8];
    const float* Wq       = (const float*)d_in[9];
    const float* bq       = (const float*)d_in[10];
    const float* Wk       = (const float*)d_in[11];
    const float* bk       = (const float*)d_in[12];
    const float* Wv       = (const float*)d_in[13];
    const float* bv       = (const float*)d_in[14];
    const float* Wp       = (const float*)d_in[15];
    const float* bp       = (const float*)d_in[16];
    const float* ln_pre_g = (const float*)d_in[17];
    const float* ln_pre_b = (const float*)d_in[18];
    const float* W1       = (const float*)d_in[19];
    const float* b1       = (const float*)d_in[20];
    const float* W2       = (const float*)d_in[21];
    const float* b2       = (const float*)d_in[22];
    const float* ln_po_g  = (const float*)d_in[23];
    const float* ln_po_b  = (const float*)d_in[24];
    float* out = (float*)d_out;

    __half *qn, *kn, *vn, *qh, *kh, *vh, *at, *z0, *z1, *h1;
    __half *Wqh, *Wkh, *Wvh, *Wph, *W1h, *W2h;
    float *z2, *muq, *rsq, *muk, *rsk, *muv, *rsv, *mu2, *rs2;
    cudaGetSymbolAddress((void**)&qn, g_qn);
    cudaGetSymbolAddress((void**)&kn, g_kn);
    cudaGetSymbolAddress((void**)&vn, g_vn);
    cudaGetSymbolAddress((void**)&qh, g_qh);
    cudaGetSymbolAddress((void**)&kh, g_kh);
    cudaGetSymbolAddress((void**)&vh, g_vh);
    cudaGetSymbolAddress((void**)&at, g_at);
    cudaGetSymbolAddress((void**)&z0, g_z0);
    cudaGetSymbolAddress((void**)&z1, g_z1);
    cudaGetSymbolAddress((void**)&h1, g_h1);
    cudaGetSymbolAddress((void**)&z2, g_z2);
    cudaGetSymbolAddress((void**)&Wqh, g_Wqh);
    cudaGetSymbolAddress((void**)&Wkh, g_Wkh);
    cudaGetSymbolAddress((void**)&Wvh, g_Wvh);
    cudaGetSymbolAddress((void**)&Wph, g_Wph);
    cudaGetSymbolAddress((void**)&W1h, g_W1h);
    cudaGetSymbolAddress((void**)&W2h, g_W2h);
    cudaGetSymbolAddress((void**)&muq, g_muq);
    cudaGetSymbolAddress((void**)&rsq, g_rsq);
    cudaGetSymbolAddress((void**)&muk, g_muk);
    cudaGetSymbolAddress((void**)&rsk, g_rsk);
    cudaGetSymbolAddress((void**)&muv, g_muv);
    cudaGetSymbolAddress((void**)&rsv, g_rsv);
    cudaGetSymbolAddress((void**)&mu2, g_mu2);
    cudaGetSymbolAddress((void**)&rs2, g_rs2);

    dim3 tblk(32, 8);

    // 0) weights -> fp16
    f2h<<<(CDIM * CDIM / 2 + 255) / 256, 256>>>(Wq, Wqh, CDIM * CDIM / 2);
    f2h<<<(CDIM * CDIM / 2 + 255) / 256, 256>>>(Wk, Wkh, CDIM * CDIM / 2);
    f2h<<<(CDIM * CDIM / 2 + 255) / 256, 256>>>(Wv, Wvh, CDIM * CDIM / 2);
    f2h<<<(CDIM * CDIM / 2 + 255) / 256, 256>>>(Wp, Wph, CDIM * CDIM / 2);
    f2h<<<(CDIM * FF / 2 + 255) / 256, 256>>>(W1, W1h, CDIM * FF / 2);
    f2h<<<(FF * CDIM / 2 + 255) / 256, 256>>>(W2, W2h, FF * CDIM / 2);

    // 1) input LNs (channel-major) + transpose to token-major fp16
    ln_stats_cm<<<NQ / 256, 256>>>(q, muq, rsq, NQ);
    ln_stats_cm<<<NKV / 256, 256>>>(k, muk, rsk, NKV);
    ln_stats_cm<<<NKV / 256, 256>>>(v, muv, rsv, NKV);
    ln_apply_t_cm<<<dim3(NQ / 32, CDIM / 32), tblk>>>(q, muq, rsq, ln_q_g, ln_q_b, qn, NQ);
    ln_apply_t_cm<<<dim3(NKV / 32, CDIM / 32), tblk>>>(k, muk, rsk, ln_k_g, ln_k_b, kn, NKV);
    ln_apply_t_cm<<<dim3(NKV / 32, CDIM / 32), tblk>>>(v, muv, rsv, ln_v_g, ln_v_b, vn, NKV);

    // 2) QKV projections (fp16 tensor cores)
    hgemm<<<dim3(CDIM / 128, NQ / 128), 256>>>(qn, Wqh, bq, nullptr, qh, nullptr, NQ, CDIM, CDIM, 0);
    hgemm<<<dim3(CDIM / 128, NKV / 128), 256>>>(kn, Wkh, bk, nullptr, kh, nullptr, NKV, CDIM, CDIM, 0);
    hgemm<<<dim3(CDIM / 128, NKV / 128), 256>>>(vn, Wvh, bv, nullptr, vh, nullptr, NKV, CDIM, CDIM, 0);

    // 3) flash attention (fp16 mma)
    attn_h<<<dim3(NQ / 64, HEADS), 128>>>(qh, kh, vh, at);

    // 4) output projection + pre-LN
    hgemm<<<dim3(CDIM / 128, NQ / 128), 256>>>(at, Wph, bp, nullptr, z0, nullptr, NQ, CDIM, CDIM, 0);
    ln_rows_h<<<NQ, 256>>>(z0, ln_pre_g, ln_pre_b, z1);

    // 5) MLP: gelu GEMM then residual GEMM (fp32 out)
    hgemm<<<dim3(FF / 128, NQ / 128), 256>>>(z1, W1h, b1, nullptr, h1, nullptr, NQ, FF, CDIM, 1);
    hgemm<<<dim3(CDIM / 128, NQ / 128), 256>>>(h1, W2h, b2, z1, nullptr, z2, NQ, CDIM, FF, 0);

    // 6) post-LN fused with transpose back to (C, N)
    row_stats<<<NQ, 256>>>(z2, mu2, rs2);
    ln_apply_t_rm<<<dim3(NQ / 32, CDIM / 32), tblk>>>(z2, mu2, rs2, ln_po_g, ln_po_b, out, NQ);
}

// round 3
// speedup vs baseline: 5.0960x; 1.4030x over previous
#include <cuda_runtime.h>
#include <cuda_fp16.h>
#include <mma.h>
#include <math.h>

using namespace nvcuda;

#define NQ     8192
#define NKV    2048
#define CDIM   512
#define HEADS  8
#define DH     64
#define FF     1024
#define LN_EPS 1e-5f

// ---------------- scratch (device globals) ----------------
__device__ __half g_qn[NQ * CDIM];
__device__ __half g_kn[NKV * CDIM];
__device__ __half g_vn[NKV * CDIM];
__device__ __half g_qh[NQ * CDIM];
__device__ __half g_kh[NKV * CDIM];
__device__ __half g_vh[NKV * CDIM];
__device__ __half g_at[NQ * CDIM];
__device__ __half g_z0[NQ * CDIM];
__device__ __half g_z1[NQ * CDIM];
__device__ __half g_h1[NQ * FF];
__device__ float  g_z2[NQ * CDIM];
__device__ __half g_Wqh[CDIM * CDIM];
__device__ __half g_Wkh[CDIM * CDIM];
__device__ __half g_Wvh[CDIM * CDIM];
__device__ __half g_Wph[CDIM * CDIM];
__device__ __half g_W1h[CDIM * FF];
__device__ __half g_W2h[FF * CDIM];

// ---------------- async copy helpers ----------------
__device__ __forceinline__ void cp16(void* sdst, const void* gsrc) {
    unsigned d = (unsigned)__cvta_generic_to_shared(sdst);
    asm volatile("cp.async.cg.shared.global [%0], [%1], 16;\n" :: "r"(d), "l"(gsrc));
}
__device__ __forceinline__ void cp_commit() {
    asm volatile("cp.async.commit_group;\n");
}
__device__ __forceinline__ void cp_wait1() {
    asm volatile("cp.async.wait_group 1;\n");
}
__device__ __forceinline__ void cp_wait0() {
    asm volatile("cp.async.wait_group 0;\n");
}

// ---------------- ldmatrix helpers ----------------
__device__ __forceinline__ void ldsm_x2(unsigned& r0, unsigned& r1, const __half* p) {
    unsigned a = (unsigned)__cvta_generic_to_shared(p);
    asm volatile("ldmatrix.sync.aligned.m8n8.x2.shared.b16 {%0,%1}, [%2];\n"
                 : "=r"(r0), "=r"(r1) : "r"(a));
}
__device__ __forceinline__ void ldsm_x2_t(unsigned& r0, unsigned& r1, const __half* p) {
    unsigned a = (unsigned)__cvta_generic_to_shared(p);
    asm volatile("ldmatrix.sync.aligned.m8n8.x2.trans.shared.b16 {%0,%1}, [%2];\n"
                 : "=r"(r0), "=r"(r1) : "r"(a));
}

// ---------------- mma.sync helper ----------------
__device__ __forceinline__ void mma16816(float* c, const unsigned* a, const unsigned* b) {
    asm volatile(
        "mma.sync.aligned.m16n8k16.row.col.f32.f16.f16.f32 "
        "{%0,%1,%2,%3}, {%4,%5,%6,%7}, {%8,%9}, {%0,%1,%2,%3};"
        : "+f"(c[0]), "+f"(c[1]), "+f"(c[2]), "+f"(c[3])
        : "r"(a[0]), "r"(a[1]), "r"(a[2]), "r"(a[3]), "r"(b[0]), "r"(b[1]));
}

// ---------------- all weight converts in one launch ----------------
__global__ void f2h_all(const float* Wq, const float* Wk, const float* Wv,
                        const float* Wp, const float* W1, const float* W2,
                        __half* Wqh, __half* Wkh, __half* Wvh,
                        __half* Wph, __half* W1h, __half* W2h) {
    int i = blockIdx.x * 256 + threadIdx.x;   // pair index
    const float* s; __half* d; int o;
    if      (i <  131072) { s = Wq; d = Wqh; o = i; }
    else if (i <  262144) { s = Wk; d = Wkh; o = i - 131072; }
    else if (i <  393216) { s = Wv; d = Wvh; o = i - 262144; }
    else if (i <  524288) { s = Wp; d = Wph; o = i - 393216; }
    else if (i <  786432) { s = W1; d = W1h; o = i - 524288; }
    else                  { s = W2; d = W2h; o = i - 786432; }
    float2 v = ((const float2*)s)[o];
    ((half2*)d)[o] = __floats2half2_rn(v.x, v.y);
}

// ---------------- fused channel-major LN: stats + apply + transpose, 16 tokens/block ----------------
#define LDT 17
__global__ __launch_bounds__(256) void ln_in_fused(
        const float* __restrict__ x, const float* __restrict__ g,
        const float* __restrict__ b, __half* __restrict__ y, int N) {
    __shared__ float t[512 * LDT];
    __shared__ float smu[16], srs[16];
    int n0 = blockIdx.x * 16, tid = threadIdx.x;
#pragma unroll
    for (int p = 0; p < 32; p++) {
        int ch = p * 16 + (tid >> 4), tok = tid & 15;
        t[ch * LDT + tok] = x[(size_t)ch * N + n0 + tok];
    }
    __syncthreads();
    int w = tid >> 5, lane = tid & 31;
    int tok = 2 * w + (lane >> 4), lid = lane & 15;
    float s = 0.f, s2 = 0.f;
#pragma unroll
    for (int i = 0; i < 32; i++) {
        float v = t[(lid + i * 16) * LDT + tok];
        s += v; s2 += v * v;
    }
#pragma unroll
    for (int o = 1; o < 16; o <<= 1) {
        s  += __shfl_xor_sync(0xffffffffu, s,  o);
        s2 += __shfl_xor_sync(0xffffffffu, s2, o);
    }
    if (lid == 0) {
        float m = s * (1.0f / CDIM);
        smu[tok] = m;
        srs[tok] = rsqrtf(s2 * (1.0f / CDIM) - m * m + LN_EPS);
    }
    __syncthreads();
#pragma unroll
    for (int p = 0; p < 16; p++) {
        int flat = p * 256 + tid;
        int tk = flat >> 8, ch = (flat & 255) * 2;
        float mu = smu[tk], rs = srs[tk];
        float v0 = (t[ch * LDT + tk] - mu) * rs * g[ch] + b[ch];
        float v1 = (t[(ch + 1) * LDT + tk] - mu) * rs * g[ch + 1] + b[ch + 1];
        ((half2*)(y + (size_t)(n0 + tk) * CDIM))[ch >> 1] = __floats2half2_rn(v0, v1);
    }
}

// ---------------- fused row LN + transpose out: 16 tokens/block ----------------
#define LDZ 513
__global__ __launch_bounds__(256) void ln_out_fused(
        const float* __restrict__ z, const float* __restrict__ g,
        const float* __restrict__ b, float* __restrict__ out, int N) {
    __shared__ float t[16 * LDZ];
    __shared__ float smu[16], srs[16];
    int n0 = blockIdx.x * 16, tid = threadIdx.x;
#pragma unroll
    for (int p = 0; p < 8; p++) {
        int f4 = p * 256 + tid;             // 2048 float4 total
        int tok = f4 >> 7, ch = (f4 & 127) * 4;
        float4 v = ((const float4*)(z + (size_t)(n0 + tok) * CDIM))[f4 & 127];
        t[tok * LDZ + ch] = v.x; t[tok * LDZ + ch + 1] = v.y;
        t[tok * LDZ + ch + 2] = v.z; t[tok * LDZ + ch + 3] = v.w;
    }
    __syncthreads();
    int w = tid >> 5, lane = tid & 31;
    int tok = 2 * w + (lane >> 4), lid = lane & 15;
    float s = 0.f, s2 = 0.f;
#pragma unroll
    for (int i = 0; i < 32; i++) {
        float v = t[tok * LDZ + lid + i * 16];
        s += v; s2 += v * v;
    }
#pragma unroll
    for (int o = 1; o < 16; o <<= 1) {
        s  += __shfl_xor_sync(0xffffffffu, s,  o);
        s2 += __shfl_xor_sync(0xffffffffu, s2, o);
    }
    if (lid == 0) {
        float m = s * (1.0f / CDIM);
        smu[tok] = m;
        srs[tok] = rsqrtf(s2 * (1.0f / CDIM) - m * m + LN_EPS);
    }
    __syncthreads();
#pragma unroll
    for (int p = 0; p < 32; p++) {
        int flat = p * 256 + tid;
        int ch = flat >> 4, tk = flat & 15;
        out[(size_t)ch * N + n0 + tk] =
            (t[tk * LDZ + ch] - smu[tk]) * srs[tk] * g[ch] + b[ch];
    }
}

// ---------------- row LN fp16 -> fp16 ----------------
__global__ void ln_rows_h(const __half* __restrict__ x, const float* __restrict__ g,
                          const float* __restrict__ b, __half* __restrict__ y) {
    int row = blockIdx.x;
    int tid = threadIdx.x;
    const __half* xr = x + (size_t)row * CDIM;
    float v0 = __half2float(xr[tid]), v1 = __half2float(xr[tid + 256]);
    float s = v0 + v1, s2 = v0 * v0 + v1 * v1;
#pragma unroll
    for (int o = 16; o > 0; o >>= 1) {
        s  += __shfl_xor_sync(0xffffffffu, s,  o);
        s2 += __shfl_xor_sync(0xffffffffu, s2, o);
    }
    __shared__ float sw[8], sw2[8];
    if ((tid & 31) == 0) { sw[tid >> 5] = s; sw2[tid >> 5] = s2; }
    __syncthreads();
    float ts = 0.f, ts2 = 0.f;
#pragma unroll
    for (int i = 0; i < 8; i++) { ts += sw[i]; ts2 += sw2[i]; }
    float m = ts * (1.0f / CDIM);
    float rstd = rsqrtf(ts2 * (1.0f / CDIM) - m * m + LN_EPS);
    __half* yr = y + (size_t)row * CDIM;
    yr[tid]       = __float2half_rn((v0 - m) * rstd * g[tid]       + b[tid]);
    yr[tid + 256] = __float2half_rn((v1 - m) * rstd * g[tid + 256] + b[tid + 256]);
}

// ---------------- fp16 tensor-core GEMM: 128x128 tile, BK=32, cp.async double-buffered ----------------
#define LDA_S 40
#define LDB_S 136
__global__ __launch_bounds__(256) void hgemm(
        const __half* __restrict__ A, const __half* __restrict__ B,
        const float* __restrict__ bias, const __half* __restrict__ res,
        __half* __restrict__ Ch, float* __restrict__ Cf,
        int M, int N, int K, int doGelu) {
    __shared__ __half As[2][128 * LDA_S];
    __shared__ __half Bs[2][32 * LDB_S];
    __shared__ float  sc[8][16 * 20];

    int tid = threadIdx.x;
    int lane = tid & 31;
    int w = tid >> 5;
    int wm = w >> 1, wn = w & 1;
    int n0 = blockIdx.x * 128, m0 = blockIdx.y * 128;

    wmma::fragment<wmma::accumulator, 16, 16, 16, float> acc[2][4];
#pragma unroll
    for (int i = 0; i < 2; i++)
#pragma unroll
        for (int j = 0; j < 4; j++) wmma::fill_fragment(acc[i][j], 0.f);

    int ar = tid >> 1, ac = (tid & 1) * 16;
    int br = tid >> 3, bc = (tid & 7) * 16;
    const __half* apb = A + (size_t)(m0 + ar) * K + ac;
    const __half* bpb = B + (size_t)br * N + n0 + bc;

    // prefetch tile 0
    cp16(&As[0][ar * LDA_S + ac],     apb);
    cp16(&As[0][ar * LDA_S + ac + 8], apb + 8);
    cp16(&Bs[0][br * LDB_S + bc],     bpb);
    cp16(&Bs[0][br * LDB_S + bc + 8], bpb + 8);
    cp_commit();

    int nT = K >> 5;
    for (int t = 0; t < nT; t++) {
        int buf = t & 1;
        if (t + 1 < nT) {
            int k0 = (t + 1) * 32;
            cp16(&As[buf ^ 1][ar * LDA_S + ac],     apb + k0);
            cp16(&As[buf ^ 1][ar * LDA_S + ac + 8], apb + k0 + 8);
            cp16(&Bs[buf ^ 1][br * LDB_S + bc],     bpb + (size_t)k0 * N);
            cp16(&Bs[buf ^ 1][br * LDB_S + bc + 8], bpb + (size_t)k0 * N + 8);
            cp_commit();
            cp_wait1();
        } else {
            cp_wait0();
        }
        __syncthreads();
#pragma unroll
        for (int ks = 0; ks < 2; ks++) {
            wmma::fragment<wmma::matrix_a, 16, 16, 16, __half, wmma::row_major> af[2];
            wmma::fragment<wmma::matrix_b, 16, 16, 16, __half, wmma::row_major> bf[4];
#pragma unroll
            for (int i = 0; i < 2; i++)
                wmma::load_matrix_sync(af[i], &As[buf][(32 * wm + 16 * i) * LDA_S + 16 * ks], LDA_S);
#pragma unroll
            for (int j = 0; j < 4; j++)
                wmma::load_matrix_sync(bf[j], &Bs[buf][(16 * ks) * LDB_S + 64 * wn + 16 * j], LDB_S);
#pragma unroll
            for (int i = 0; i < 2; i++)
#pragma unroll
                for (int j = 0; j < 4; j++)
                    wmma::mma_sync(acc[i][j], af[i], bf[j], acc[i][j]);
        }
        __syncthreads();
    }

    int lr = lane >> 1, lc0 = (lane & 1) * 8;
#pragma unroll
    for (int i = 0; i < 2; i++) {
#pragma unroll
        for (int j = 0; j < 4; j++) {
            wmma::store_matrix_sync(&sc[w][0], acc[i][j], 20, wmma::mem_row_major);
            __syncwarp();
            int row = m0 + 32 * wm + 16 * i + lr;
            int col = n0 + 64 * wn + 16 * j + lc0;
            float vv[8];
#pragma unroll
            for (int e = 0; e < 8; e++) {
                float c = sc[w][lr * 20 + lc0 + e] + bias[col + e];
                if (doGelu) c = 0.5f * c * (1.0f + erff(c * 0.70710678118654752f));
                if (res) c += __half2float(res[(size_t)row * N + col + e]);
                vv[e] = c;
            }
            if (Ch) {
                half2* dst = (half2*)&Ch[(size_t)row * N + col];
                dst[0] = __floats2half2_rn(vv[0], vv[1]);
                dst[1] = __floats2half2_rn(vv[2], vv[3]);
                dst[2] = __floats2half2_rn(vv[4], vv[5]);
                dst[3] = __floats2half2_rn(vv[6], vv[7]);
            }
            if (Cf) {
                float4* dst = (float4*)&Cf[(size_t)row * N + col];
                dst[0] = make_float4(vv[0], vv[1], vv[2], vv[3]);
                dst[1] = make_float4(vv[4], vv[5], vv[6], vv[7]);
            }
            __syncwarp();
        }
    }
}

// ---------------- flash attention: 128 q x 1 head / block, 8 warps, cp.async + ldmatrix ----------------
#define LDK 72
__global__ __launch_bounds__(256) void attn_h(
        const __half* __restrict__ qh, const __half* __restrict__ kh,
        const __half* __restrict__ vh, __half* __restrict__ outp) {
    // SM[buf]: first 64*LDK = K tile [tok][d], next 64*LDK = V tile [tok][d]
    __shared__ __half SM[2][2 * 64 * LDK];

    const int tid = threadIdx.x;
    const int lane = tid & 31;
    const int w = tid >> 5;             // 0..7, owns q rows 16w..16w+15
    const int h = blockIdx.y;
    const int q0 = blockIdx.x * 128;
    const int tq = lane >> 2;           // 0..7
    const int tr = lane & 3;            // 0..3

    // ---- stage Q (128 x 64, scaled) into SM[0] viewed as 128 rows ----
    {
        __half* Qs = &SM[0][0];
        int r = tid >> 1, cb = (tid & 1) * 32;
        const __half* src = qh + (size_t)(q0 + r) * CDIM + h * DH + cb;
        half2 scale = __half2half2(__float2half(0.125f));
        half2* d = (half2*)&Qs[r * LDK + cb];
#pragma unroll
        for (int i = 0; i < 16; i++)
            d[i] = __hmul2(((const half2*)src)[i], scale);
    }
    __syncthreads();
    unsigned qa[4][4];
    {
        const __half* Qs = &SM[0][0];
        int r0 = 16 * w + tq, r1 = r0 + 8;
#pragma unroll
        for (int c = 0; c < 4; c++) {
            int d0 = c * 16 + 2 * tr;
            qa[c][0] = *(const unsigned*)&Qs[r0 * LDK + d0];
            qa[c][1] = *(const unsigned*)&Qs[r1 * LDK + d0];
            qa[c][2] = *(const unsigned*)&Qs[r0 * LDK + d0 + 8];
            qa[c][3] = *(const unsigned*)&Qs[r1 * LDK + d0 + 8];
        }
    }
    __syncthreads();

    // cp.async loader: 256 threads, K tile 64x64 (512 x16B) + V tile -> 4 chunks/thread
    const int lrow = tid >> 2;            // 0..63
    const int lcol = (tid & 3) * 16;      // 0,16,32,48

    float m0 = -1e30f, m1 = -1e30f, l0 = 0.f, l1 = 0.f;
    float oacc[8][4];
#pragma unroll
    for (int j = 0; j < 8; j++)
#pragma unroll
        for (int r = 0; r < 4; r++) oacc[j][r] = 0.f;

    // prefetch tile 0
    {
        const __half* kg = kh + (size_t)lrow * CDIM + h * DH + lcol;
        const __half* vg = vh + (size_t)lrow * CDIM + h * DH + lcol;
        cp16(&SM[0][lrow * LDK + lcol],     kg);
        cp16(&SM[0][lrow * LDK + lcol + 8], kg + 8);
        cp16(&SM[0][64 * LDK + lrow * LDK + lcol],     vg);
        cp16(&SM[0][64 * LDK + lrow * LDK + lcol + 8], vg + 8);
        cp_commit();
    }

    const int NT = NKV / 64;   // 32
    for (int it = 0; it < NT; it++) {
        int buf = it & 1;
        if (it + 1 < NT) {
            int kb = (it + 1) * 64;
            const __half* kg = kh + (size_t)(kb + lrow) * CDIM + h * DH + lcol;
            const __half* vg = vh + (size_t)(kb + lrow) * CDIM + h * DH + lcol;
            cp16(&SM[buf ^ 1][lrow * LDK + lcol],     kg);
            cp16(&SM[buf ^ 1][lrow * LDK + lcol + 8], kg + 8);
            cp16(&SM[buf ^ 1][64 * LDK + lrow * LDK + lcol],     vg);
            cp16(&SM[buf ^ 1][64 * LDK + lrow * LDK + lcol + 8], vg + 8);
            cp_commit();
            cp_wait1();
        } else {
            cp_wait0();
        }
        __syncthreads();

        const __half* Kt = &SM[buf][0];
        const __half* Vt = &SM[buf][64 * LDK];

        // ---- S = Q @ K^T ----
        float sacc[8][4];
#pragma unroll
        for (int j = 0; j < 8; j++)
#pragma unroll
            for (int r = 0; r < 4; r++) sacc[j][r] = 0.f;
#pragma unroll
        for (int j = 0; j < 8; j++) {
#pragma unroll
            for (int c = 0; c < 4; c++) {
                unsigned bb[2];
                ldsm_x2(bb[0], bb[1],
                        &Kt[(j * 8 + (lane & 7)) * LDK + c * 16 + (lane & 8)]);
                mma16816(sacc[j], qa[c], bb);
            }
        }

        // ---- online softmax ----
        float mx0 = -1e30f, mx1 = -1e30f;
#pragma unroll
        for (int j = 0; j < 8; j++) {
            mx0 = fmaxf(mx0, fmaxf(sacc[j][0], sacc[j][1]));
            mx1 = fmaxf(mx1, fmaxf(sacc[j][2], sacc[j][3]));
        }
        mx0 = fmaxf(mx0, __shfl_xor_sync(0xffffffffu, mx0, 1));
        mx0 = fmaxf(mx0, __shfl_xor_sync(0xffffffffu, mx0, 2));
        mx1 = fmaxf(mx1, __shfl_xor_sync(0xffffffffu, mx1, 1));
        mx1 = fmaxf(mx1, __shfl_xor_sync(0xffffffffu, mx1, 2));
        float mn0 = fmaxf(m0, mx0), mn1 = fmaxf(m1, mx1);
        float corr0 = __expf(m0 - mn0), corr1 = __expf(m1 - mn1);
        m0 = mn0; m1 = mn1;
        float s0 = 0.f, s1 = 0.f;
#pragma unroll
        for (int j = 0; j < 8; j++) {
            sacc[j][0] = __expf(sacc[j][0] - mn0);
            sacc[j][1] = __expf(sacc[j][1] - mn0);
            sacc[j][2] = __expf(sacc[j][2] - mn1);
            sacc[j][3] = __expf(sacc[j][3] - mn1);
            s0 += sacc[j][0] + sacc[j][1];
            s1 += sacc[j][2] + sacc[j][3];
        }
        s0 += __shfl_xor_sync(0xffffffffu, s0, 1);
        s0 += __shfl_xor_sync(0xffffffffu, s0, 2);
        s1 += __shfl_xor_sync(0xffffffffu, s1, 1);
        s1 += __shfl_xor_sync(0xffffffffu, s1, 2);
        l0 = l0 * corr0 + s0;
        l1 = l1 * corr1 + s1;
#pragma unroll
        for (int j = 0; j < 8; j++) {
            oacc[j][0] *= corr0; oacc[j][1] *= corr0;
            oacc[j][2] *= corr1; oacc[j][3] *= corr1;
        }

        // ---- P fragments from S accumulators (register-only) ----
        unsigned pa[4][4];
#pragma unroll
        for (int c = 0; c < 4; c++) {
            half2 h0 = __floats2half2_rn(sacc[2 * c][0], sacc[2 * c][1]);
            half2 h1v = __floats2half2_rn(sacc[2 * c][2], sacc[2 * c][3]);
            half2 h2 = __floats2half2_rn(sacc[2 * c + 1][0], sacc[2 * c + 1][1]);
            half2 h3 = __floats2half2_rn(sacc[2 * c + 1][2], sacc[2 * c + 1][3]);
            pa[c][0] = *(unsigned*)&h0;
            pa[c][1] = *(unsigned*)&h1v;
            pa[c][2] = *(unsigned*)&h2;
            pa[c][3] = *(unsigned*)&h3;
        }

        // ---- O += P @ V (V row-major, ldmatrix.trans) ----
#pragma unroll
        for (int j = 0; j < 8; j++) {
#pragma unroll
            for (int c = 0; c < 4; c++) {
                unsigned bb[2];
                ldsm_x2_t(bb[0], bb[1],
                          &Vt[(c * 16 + (lane & 15)) * LDK + j * 8]);
                mma16816(oacc[j], pa[c], bb);
            }
        }
        __syncthreads();
    }

    // ---- normalize + write ----
    float inv0 = 1.0f / l0, inv1 = 1.0f / l1;
    int r0 = q0 + 16 * w + tq, r1 = r0 + 8;
#pragma unroll
    for (int j = 0; j < 8; j++) {
        int col = h * DH + j * 8 + 2 * tr;
        *(half2*)&outp[(size_t)r0 * CDIM + col] =
            __floats2half2_rn(oacc[j][0] * inv0, oacc[j][1] * inv0);
        *(half2*)&outp[(size_t)r1 * CDIM + col] =
            __floats2half2_rn(oacc[j][2] * inv1, oacc[j][3] * inv1);
    }
}

// ---------------- launch ----------------
extern "C" void kernel_launch(void* const* d_in, const int* in_sizes, int n_in,
                              void* d_out, int out_size) {
    const float* q        = (const float*)d_in[0];
    const float* k        = (const float*)d_in[1];
    const float* v        = (const float*)d_in[2];
    const float* ln_q_g   = (const float*)d_in[3];
    const float* ln_q_b   = (const float*)d_in[4];
    const float* ln_k_g   = (const float*)d_in[5];
    const float* ln_k_b   = (const float*)d_in[6];
    const float* ln_v_g   = (const float*)d_in[7];
    const float* ln_v_b   = (const float*)d_in[8];
    const float* Wq       = (const float*)d_in[9];
    const float* bq       = (const float*)d_in[10];
    const float* Wk       = (const float*)d_in[11];
    const float* bk       = (const float*)d_in[12];
    const float* Wv       = (const float*)d_in[13];
    const float* bv       = (const float*)d_in[14];
    const float* Wp       = (const float*)d_in[15];
    const float* bp       = (const float*)d_in[16];
    const float* ln_pre_g = (const float*)d_in[17];
    const float* ln_pre_b = (const float*)d_in[18];
    const float* W1       = (const float*)d_in[19];
    const float* b1       = (const float*)d_in[20];
    const float* W2       = (const float*)d_in[21];
    const float* b2       = (const float*)d_in[22];
    const float* ln_po_g  = (const float*)d_in[23];
    const float* ln_po_b  = (const float*)d_in[24];
    float* out = (float*)d_out;

    __half *qn, *kn, *vn, *qh, *kh, *vh, *at, *z0, *z1, *h1;
    __half *Wqh, *Wkh, *Wvh, *Wph, *W1h, *W2h;
    float *z2;
    cudaGetSymbolAddress((void**)&qn, g_qn);
    cudaGetSymbolAddress((void**)&kn, g_kn);
    cudaGetSymbolAddress((void**)&vn, g_vn);
    cudaGetSymbolAddress((void**)&qh, g_qh);
    cudaGetSymbolAddress((void**)&kh, g_kh);
    cudaGetSymbolAddress((void**)&vh, g_vh);
    cudaGetSymbolAddress((void**)&at, g_at);
    cudaGetSymbolAddress((void**)&z0, g_z0);
    cudaGetSymbolAddress((void**)&z1, g_z1);
    cudaGetSymbolAddress((void**)&h1, g_h1);
    cudaGetSymbolAddress((void**)&z2, g_z2);
    cudaGetSymbolAddress((void**)&Wqh, g_Wqh);
    cudaGetSymbolAddress((void**)&Wkh, g_Wkh);
    cudaGetSymbolAddress((void**)&Wvh, g_Wvh);
    cudaGetSymbolAddress((void**)&Wph, g_Wph);
    cudaGetSymbolAddress((void**)&W1h, g_W1h);
    cudaGetSymbolAddress((void**)&W2h, g_W2h);

    // 0) all weights -> fp16 (one launch)
    f2h_all<<<4096, 256>>>(Wq, Wk, Wv, Wp, W1, W2, Wqh, Wkh, Wvh, Wph, W1h, W2h);

    // 1) fused input LNs (stats + apply + transpose)
    ln_in_fused<<<NQ / 16, 256>>>(q, ln_q_g, ln_q_b, qn, NQ);
    ln_in_fused<<<NKV / 16, 256>>>(k, ln_k_g, ln_k_b, kn, NKV);
    ln_in_fused<<<NKV / 16, 256>>>(v, ln_v_g, ln_v_b, vn, NKV);

    // 2) QKV projections
    hgemm<<<dim3(CDIM / 128, NQ / 128), 256>>>(qn, Wqh, bq, nullptr, qh, nullptr, NQ, CDIM, CDIM, 0);
    hgemm<<<dim3(CDIM / 128, NKV / 128), 256>>>(kn, Wkh, bk, nullptr, kh, nullptr, NKV, CDIM, CDIM, 0);
    hgemm<<<dim3(CDIM / 128, NKV / 128), 256>>>(vn, Wvh, bv, nullptr, vh, nullptr, NKV, CDIM, CDIM, 0);

    // 3) flash attention
    attn_h<<<dim3(NQ / 128, HEADS), 256>>>(qh, kh, vh, at);

    // 4) output projection + pre-LN
    hgemm<<<dim3(CDIM / 128, NQ / 128), 256>>>(at, Wph, bp, nullptr, z0, nullptr, NQ, CDIM, CDIM, 0);
    ln_rows_h<<<NQ, 256>>>(z0, ln_pre_g, ln_pre_b, z1);

    // 5) MLP
    hgemm<<<dim3(FF / 128, NQ / 128), 256>>>(z1, W1h, b1, nullptr, h1, nullptr, NQ, FF, CDIM, 1);
    hgemm<<<dim3(CDIM / 128, NQ / 128), 256>>>(h1, W2h, b2, z1, nullptr, z2, NQ, CDIM, FF, 0);

    // 6) post-LN + transpose back to (C, N)
    ln_out_fused<<<NQ / 16, 256>>>(z2, ln_po_g, ln_po_b, out, NQ);
}